// round 15
// baseline (speedup 1.0000x reference)
#include <cuda_runtime.h>
#include <math.h>

#define Bsz 4
#define Ssz 2048
#define Dsz 768
#define Hsz 12
#define HDsz 64
#define BH (Bsz*Hsz)          // 48
#define MROWS (Bsz*Ssz)       // 8192
#define N_QKV (3*Dsz)         // 2304

// ---------------- scratch (no allocations allowed) ----------------
__device__ float g_Q[BH * Ssz * HDsz];   // [b,h,s,hd]
__device__ float g_K[BH * Ssz * HDsz];
__device__ float g_V[BH * Ssz * HDsz];
__device__ float g_attn[MROWS * Dsz];    // [b,s, h*64+hd]
__device__ float g_x[MROWS * Dsz];       // proj + bias + residual

// ---------------- bf16 split helpers ----------------
__device__ __forceinline__ float btrunc(float a) {
    return __uint_as_float(__float_as_uint(a) & 0xFFFF0000u);
}
__device__ __forceinline__ unsigned packbf(float ah, float bh) {
    return (__float_as_uint(ah) >> 16) | (__float_as_uint(bh) & 0xFFFF0000u);
}
__device__ __forceinline__ void splitp(float a, float b, unsigned& hp, unsigned& lp) {
    float ah = btrunc(a), bh = btrunc(b);
    hp = packbf(ah, bh);
    lp = packbf(btrunc(a - ah), btrunc(b - bh));
}
__device__ __forceinline__ void mmabf(float c[4], const unsigned a[4],
                                      unsigned b0, unsigned b1) {
    asm volatile(
        "mma.sync.aligned.m16n8k16.row.col.f32.bf16.bf16.f32 "
        "{%0,%1,%2,%3}, {%4,%5,%6,%7}, {%8,%9}, {%0,%1,%2,%3};\n"
        : "+f"(c[0]), "+f"(c[1]), "+f"(c[2]), "+f"(c[3])
        : "r"(a[0]), "r"(a[1]), "r"(a[2]), "r"(a[3]), "r"(b0), "r"(b1));
}
__device__ __forceinline__ unsigned sm_u32(const void* p) {
    unsigned r;
    asm("{ .reg .u64 t; cvta.to.shared.u64 t, %1; cvt.u32.u64 %0, t; }"
        : "=r"(r) : "l"(p));
    return r;
}
#define LDSM4(r0,r1,r2,r3,a) \
    asm volatile("ldmatrix.sync.aligned.m8n8.x4.shared.b16 {%0,%1,%2,%3}, [%4];" \
        : "=r"(r0), "=r"(r1), "=r"(r2), "=r"(r3) : "r"(a))
#define LDSM4T(r0,r1,r2,r3,a) \
    asm volatile("ldmatrix.sync.aligned.m8n8.x4.trans.shared.b16 {%0,%1,%2,%3}, [%4];" \
        : "=r"(r0), "=r"(r1), "=r"(r2), "=r"(r3) : "r"(a))

// ============================================================
// bf16x3 GEMM core: block 128x64, BK=32, 256 thr, warp tile 32x32.
// (R13 version: prefetch + B-fragment reuse — proven)
// ============================================================
__device__ __forceinline__ void bf3_core(
    const float* __restrict__ A, const float* __restrict__ Bw,
    int NN, int m0, int n0, float acc[2][4][4],
    unsigned AH[128][17], unsigned AL[128][17],
    unsigned BHs[64][17], unsigned BLs[64][17])
{
    const int tid  = threadIdx.x;
    const int lane = tid & 31, wid = tid >> 5;
    const int g = lane >> 2, tig = lane & 3;
    const int wm = wid >> 1, wn = wid & 1;

    const int mA = tid >> 1, kqA = (tid & 1) * 16;
    const float* Ap = A + (size_t)(m0 + mA) * Dsz + kqA;
    const int kpB = tid >> 4, nqB = (tid & 15) * 4;
    const float* Bp = Bw + (size_t)(2 * kpB) * NN + n0 + nqB;

#pragma unroll
    for (int i = 0; i < 2; i++)
#pragma unroll
        for (int j = 0; j < 4; j++)
#pragma unroll
            for (int r = 0; r < 4; r++) acc[i][j][r] = 0.f;

    float4 a0 = *(const float4*)(Ap);
    float4 a1 = *(const float4*)(Ap + 4);
    float4 a2 = *(const float4*)(Ap + 8);
    float4 a3 = *(const float4*)(Ap + 12);
    float4 b0 = *(const float4*)(Bp);
    float4 b1 = *(const float4*)(Bp + NN);

#pragma unroll 1
    for (int it = 0; it < Dsz / 32; it++) {
        const int kp = kqA >> 1;
        splitp(a0.x, a0.y, AH[mA][kp+0], AL[mA][kp+0]);
        splitp(a0.z, a0.w, AH[mA][kp+1], AL[mA][kp+1]);
        splitp(a1.x, a1.y, AH[mA][kp+2], AL[mA][kp+2]);
        splitp(a1.z, a1.w, AH[mA][kp+3], AL[mA][kp+3]);
        splitp(a2.x, a2.y, AH[mA][kp+4], AL[mA][kp+4]);
        splitp(a2.z, a2.w, AH[mA][kp+5], AL[mA][kp+5]);
        splitp(a3.x, a3.y, AH[mA][kp+6], AL[mA][kp+6]);
        splitp(a3.z, a3.w, AH[mA][kp+7], AL[mA][kp+7]);
        splitp(b0.x, b1.x, BHs[nqB+0][kpB], BLs[nqB+0][kpB]);
        splitp(b0.y, b1.y, BHs[nqB+1][kpB], BLs[nqB+1][kpB]);
        splitp(b0.z, b1.z, BHs[nqB+2][kpB], BLs[nqB+2][kpB]);
        splitp(b0.w, b1.w, BHs[nqB+3][kpB], BLs[nqB+3][kpB]);
        __syncthreads();

        if (it + 1 < Dsz / 32) {
            const int k1 = (it + 1) * 32;
            a0 = *(const float4*)(Ap + k1);
            a1 = *(const float4*)(Ap + k1 + 4);
            a2 = *(const float4*)(Ap + k1 + 8);
            a3 = *(const float4*)(Ap + k1 + 12);
            b0 = *(const float4*)(Bp + (size_t)k1 * NN);
            b1 = *(const float4*)(Bp + (size_t)k1 * NN + NN);
        }

#pragma unroll
        for (int ks = 0; ks < 2; ks++) {
            const int kb = ks * 8;
            unsigned aH[2][4], aL[2][4];
#pragma unroll
            for (int mf = 0; mf < 2; mf++) {
                const int row = wm * 32 + mf * 16 + g;
                aH[mf][0] = AH[row][kb + tig];         aL[mf][0] = AL[row][kb + tig];
                aH[mf][1] = AH[row + 8][kb + tig];     aL[mf][1] = AL[row + 8][kb + tig];
                aH[mf][2] = AH[row][kb + 4 + tig];     aL[mf][2] = AL[row][kb + 4 + tig];
                aH[mf][3] = AH[row + 8][kb + 4 + tig]; aL[mf][3] = AL[row + 8][kb + 4 + tig];
            }
#pragma unroll
            for (int nf = 0; nf < 4; nf++) {
                const int n = wn * 32 + nf * 8 + g;
                unsigned bH0 = BHs[n][kb + tig], bH1 = BHs[n][kb + 4 + tig];
                unsigned bL0 = BLs[n][kb + tig], bL1 = BLs[n][kb + 4 + tig];
#pragma unroll
                for (int mf = 0; mf < 2; mf++) {
                    mmabf(acc[mf][nf], aL[mf], bH0, bH1);
                    mmabf(acc[mf][nf], aH[mf], bL0, bL1);
                    mmabf(acc[mf][nf], aH[mf], bH0, bH1);
                }
            }
        }
        __syncthreads();
    }
}

// ---------------- QKV GEMM -> scatter to g_Q/g_K/g_V ----------------
__global__ void __launch_bounds__(256)
qkv_b3(const float* __restrict__ A, const float* __restrict__ Bw)
{
    __shared__ unsigned AH[128][17], AL[128][17];
    __shared__ unsigned BHs[64][17], BLs[64][17];

    const int m0 = blockIdx.y * 128, n0 = blockIdx.x * 64;
    float acc[2][4][4];
    bf3_core(A, Bw, N_QKV, m0, n0, acc, AH, AL, BHs, BLs);

    const int tid = threadIdx.x;
    const int lane = tid & 31, wid = tid >> 5;
    const int g = lane >> 2, tig = lane & 3;
    const int wm = wid >> 1, wn = wid & 1;

    const int nbase = n0 + wn * 32;
    const int which = nbase / Dsz;
    const int h = (nbase % Dsz) >> 6;
    const int hd0 = (nbase % Dsz) & 63;
    float* dst = (which == 0) ? g_Q : (which == 1) ? g_K : g_V;
#pragma unroll
    for (int mf = 0; mf < 2; mf++) {
        const int m = m0 + wm * 32 + mf * 16 + g;
        const int b = m >> 11, s = m & 2047;
        float* r0 = dst + ((size_t)(b * Hsz + h) * Ssz + s) * HDsz + hd0;
        float* r1 = r0 + 8 * HDsz;
#pragma unroll
        for (int nf = 0; nf < 4; nf++) {
            const int hd = nf * 8 + tig * 2;
            *(float2*)(r0 + hd) = make_float2(acc[mf][nf][0], acc[mf][nf][1]);
            *(float2*)(r1 + hd) = make_float2(acc[mf][nf][2], acc[mf][nf][3]);
        }
    }
}

// ---------------- proj GEMM -> g_x = acc + bias + resid ----------------
__global__ void __launch_bounds__(256)
proj_b3(const float* __restrict__ Bw, const float* __restrict__ bias,
        const float* __restrict__ resid)
{
    __shared__ unsigned AH[128][17], AL[128][17];
    __shared__ unsigned BHs[64][17], BLs[64][17];

    const int m0 = blockIdx.y * 128, n0 = blockIdx.x * 64;
    float acc[2][4][4];
    bf3_core(g_attn, Bw, Dsz, m0, n0, acc, AH, AL, BHs, BLs);

    const int tid = threadIdx.x;
    const int lane = tid & 31, wid = tid >> 5;
    const int g = lane >> 2, tig = lane & 3;
    const int wm = wid >> 1, wn = wid & 1;

#pragma unroll
    for (int mf = 0; mf < 2; mf++) {
        const int m = m0 + wm * 32 + mf * 16 + g;
#pragma unroll
        for (int nf = 0; nf < 4; nf++) {
            const int n = n0 + wn * 32 + nf * 8 + tig * 2;
            float2 bv  = *(const float2*)(bias + n);
            float2 rv0 = *(const float2*)(resid + (size_t)m * Dsz + n);
            float2 rv1 = *(const float2*)(resid + (size_t)(m + 8) * Dsz + n);
            *(float2*)(g_x + (size_t)m * Dsz + n) =
                make_float2(acc[mf][nf][0] + bv.x + rv0.x, acc[mf][nf][1] + bv.y + rv0.y);
            *(float2*)(g_x + (size_t)(m + 8) * Dsz + n) =
                make_float2(acc[mf][nf][2] + bv.x + rv1.x, acc[mf][nf][3] + bv.y + rv1.y);
        }
    }
}

// ============================================================
// Flash attention, bf16x3 HMMA + ldmatrix fragment loads.
// 128 thr (4 warps), q-tile 128 (warp=32 q-rows, mf=2), k-tile 64.
// Q/K/V all stored row-major [row][hd-pair], stride 36 u32 (144B rows).
// Q,K: non-trans LDSM (A/B ops). V: trans LDSM (B op of P·V).
// ============================================================
#define FA_STR 36
#define ATTN_SMEM_BYTES ((2*128*FA_STR + 4*64*FA_STR + 64) * 4)  // 73984 B

__global__ void __launch_bounds__(128)
fa_tc4(const float* __restrict__ pad_mask)
{
    extern __shared__ unsigned smu[];
    unsigned* QsH = smu;                       // [128][36]
    unsigned* QsL = smu + 128 * FA_STR;
    unsigned* KsH = smu + 2 * 128 * FA_STR;    // [64][36]
    unsigned* KsL = KsH + 64 * FA_STR;
    unsigned* VsH = KsL + 64 * FA_STR;         // [64][36] rows=key
    unsigned* VsL = VsH + 64 * FA_STR;
    float* msk = (float*)(VsL + 64 * FA_STR);

    const int tid  = threadIdx.x;
    const int lane = tid & 31, wid = tid >> 5;
    const int g = lane >> 2, tig = lane & 3;
    const int l7 = lane & 7, sel = lane >> 3;
    const int qw = wid * 32;
    const int q0 = blockIdx.x * 128;
    const int bh = blockIdx.y;
    const int b = bh / Hsz, h = bh % Hsz;

    const float* Qg = g_Q + ((size_t)bh * Ssz + q0) * HDsz;
    const float* Kg = g_K + (size_t)bh * Ssz * HDsz;
    const float* Vg = g_V + (size_t)bh * Ssz * HDsz;
    const float* mk = pad_mask + b * Ssz;

    // ---- lane-static ldmatrix address components ----
    const unsigned aRow = ((sel & 1) ? 8u : 0u) + l7;   // A tiles (Q)
    const unsigned aKp  = (sel & 2) ? 4u : 0u;
    const unsigned bN   = ((sel & 2) ? 8u : 0u) + l7;   // B tiles (K)
    const unsigned bKp  = (sel & 1) ? 4u : 0u;
    const unsigned vKey = ((sel & 1) ? 8u : 0u) + l7;   // V trans tiles
    const unsigned vCol = (sel & 2) ? 4u : 0u;

    const unsigned qh_b = sm_u32(QsH), ql_b = sm_u32(QsL);
    const unsigned kh_b = sm_u32(KsH), kl_b = sm_u32(KsL);
    const unsigned vh_b = sm_u32(VsH), vl_b = sm_u32(VsL);

    const unsigned qaH0 = qh_b + ((qw + aRow) * FA_STR + aKp) * 4;
    const unsigned qaH1 = qaH0 + 16 * FA_STR * 4;
    const unsigned qaL0 = ql_b + ((qw + aRow) * FA_STR + aKp) * 4;
    const unsigned qaL1 = qaL0 + 16 * FA_STR * 4;
    const unsigned kaH  = kh_b + (bN * FA_STR + bKp) * 4;
    const unsigned kaL  = kl_b + (bN * FA_STR + bKp) * 4;
    const unsigned vaH  = vh_b + (vKey * FA_STR + vCol) * 4;
    const unsigned vaL  = vl_b + (vKey * FA_STR + vCol) * 4;

    // ---- load Q tile (scaled by 1/8), split hi/lo ----
#pragma unroll
    for (int i = 0; i < 16; i++) {
        int idx = tid + i * 128;
        int r = idx >> 4, c4 = (idx & 15) * 4;
        float4 v = *(const float4*)(Qg + r * HDsz + c4);
        v.x *= 0.125f; v.y *= 0.125f; v.z *= 0.125f; v.w *= 0.125f;
        int kp = r * FA_STR + (c4 >> 1);
        splitp(v.x, v.y, QsH[kp],     QsL[kp]);
        splitp(v.z, v.w, QsH[kp + 1], QsL[kp + 1]);
    }

    float O[2][8][4];
#pragma unroll
    for (int mf = 0; mf < 2; mf++)
#pragma unroll
        for (int i = 0; i < 8; i++)
#pragma unroll
            for (int j = 0; j < 4; j++) O[mf][i][j] = 0.f;
    float mr0[2], mr1[2], la0[2], la1[2];
#pragma unroll
    for (int mf = 0; mf < 2; mf++) { mr0[mf] = -1e30f; mr1[mf] = -1e30f; la0[mf] = 0.f; la1[mf] = 0.f; }

#pragma unroll 1
    for (int kt = 0; kt < Ssz / 64; kt++) {
        const int key0 = kt * 64;
        __syncthreads();
#pragma unroll
        for (int i = 0; i < 8; i++) {
            int idx = tid + i * 128;
            int r = idx >> 4, c4 = (idx & 15) * 4;
            int kp = r * FA_STR + (c4 >> 1);
            float4 kv = *(const float4*)(Kg + (size_t)(key0 + r) * HDsz + c4);
            splitp(kv.x, kv.y, KsH[kp],     KsL[kp]);
            splitp(kv.z, kv.w, KsH[kp + 1], KsL[kp + 1]);
            float4 vv = *(const float4*)(Vg + (size_t)(key0 + r) * HDsz + c4);
            splitp(vv.x, vv.y, VsH[kp],     VsL[kp]);
            splitp(vv.z, vv.w, VsH[kp + 1], VsL[kp + 1]);
        }
        if (tid < 64) msk[tid] = mk[key0 + tid];
        __syncthreads();

        // ---- S = Q @ K^T (bf16x3) ----
        float sacc[2][8][4];
#pragma unroll
        for (int mf = 0; mf < 2; mf++)
#pragma unroll
            for (int i = 0; i < 8; i++)
#pragma unroll
                for (int j = 0; j < 4; j++) sacc[mf][i][j] = 0.f;
#pragma unroll 1
        for (int ks = 0; ks < 4; ks++) {
            const unsigned ko = ks * 32;   // 8 u32 per ks
            unsigned aH[2][4], aL[2][4];
            LDSM4(aH[0][0], aH[0][1], aH[0][2], aH[0][3], qaH0 + ko);
            LDSM4(aH[1][0], aH[1][1], aH[1][2], aH[1][3], qaH1 + ko);
            LDSM4(aL[0][0], aL[0][1], aL[0][2], aL[0][3], qaL0 + ko);
            LDSM4(aL[1][0], aL[1][1], aL[1][2], aL[1][3], qaL1 + ko);
#pragma unroll
            for (int p = 0; p < 4; p++) {
                unsigned kh[4], kl[4];
                const unsigned po = p * (16 * FA_STR * 4);
                LDSM4(kh[0], kh[1], kh[2], kh[3], kaH + po + ko);
                LDSM4(kl[0], kl[1], kl[2], kl[3], kaL + po + ko);
#pragma unroll
                for (int mf = 0; mf < 2; mf++) {
                    mmabf(sacc[mf][2*p],   aL[mf], kh[0], kh[1]);
                    mmabf(sacc[mf][2*p],   aH[mf], kl[0], kl[1]);
                    mmabf(sacc[mf][2*p],   aH[mf], kh[0], kh[1]);
                    mmabf(sacc[mf][2*p+1], aL[mf], kh[2], kh[3]);
                    mmabf(sacc[mf][2*p+1], aH[mf], kl[2], kl[3]);
                    mmabf(sacc[mf][2*p+1], aH[mf], kh[2], kh[3]);
                }
            }
        }

        // ---- mask (scale folded into Q) ----
#pragma unroll
        for (int nf = 0; nf < 8; nf++) {
            float mv0 = msk[nf * 8 + tig * 2];
            float mv1 = msk[nf * 8 + tig * 2 + 1];
#pragma unroll
            for (int mf = 0; mf < 2; mf++) {
                sacc[mf][nf][0] = sacc[mf][nf][0] * mv0 - (1.f - mv0) * 1e10f;
                sacc[mf][nf][1] = sacc[mf][nf][1] * mv1 - (1.f - mv1) * 1e10f;
                sacc[mf][nf][2] = sacc[mf][nf][2] * mv0 - (1.f - mv0) * 1e10f;
                sacc[mf][nf][3] = sacc[mf][nf][3] * mv1 - (1.f - mv1) * 1e10f;
            }
        }

        // ---- online softmax per mf ----
#pragma unroll
        for (int mf = 0; mf < 2; mf++) {
            float tm0 = -1e30f, tm1 = -1e30f;
#pragma unroll
            for (int nf = 0; nf < 8; nf++) {
                tm0 = fmaxf(tm0, fmaxf(sacc[mf][nf][0], sacc[mf][nf][1]));
                tm1 = fmaxf(tm1, fmaxf(sacc[mf][nf][2], sacc[mf][nf][3]));
            }
            tm0 = fmaxf(tm0, __shfl_xor_sync(0xffffffffu, tm0, 1));
            tm0 = fmaxf(tm0, __shfl_xor_sync(0xffffffffu, tm0, 2));
            tm1 = fmaxf(tm1, __shfl_xor_sync(0xffffffffu, tm1, 1));
            tm1 = fmaxf(tm1, __shfl_xor_sync(0xffffffffu, tm1, 2));
            float mn0 = fmaxf(mr0[mf], tm0), mn1 = fmaxf(mr1[mf], tm1);
            float c0 = __expf(mr0[mf] - mn0), c1 = __expf(mr1[mf] - mn1);
            float s0 = 0.f, s1 = 0.f;
#pragma unroll
            for (int nf = 0; nf < 8; nf++) {
                sacc[mf][nf][0] = __expf(sacc[mf][nf][0] - mn0);
                sacc[mf][nf][1] = __expf(sacc[mf][nf][1] - mn0);
                sacc[mf][nf][2] = __expf(sacc[mf][nf][2] - mn1);
                sacc[mf][nf][3] = __expf(sacc[mf][nf][3] - mn1);
                s0 += sacc[mf][nf][0] + sacc[mf][nf][1];
                s1 += sacc[mf][nf][2] + sacc[mf][nf][3];
            }
            s0 += __shfl_xor_sync(0xffffffffu, s0, 1);
            s0 += __shfl_xor_sync(0xffffffffu, s0, 2);
            s1 += __shfl_xor_sync(0xffffffffu, s1, 1);
            s1 += __shfl_xor_sync(0xffffffffu, s1, 2);
            la0[mf] = la0[mf] * c0 + s0;
            la1[mf] = la1[mf] * c1 + s1;
            mr0[mf] = mn0; mr1[mf] = mn1;
#pragma unroll
            for (int nf = 0; nf < 8; nf++) {
                O[mf][nf][0] *= c0; O[mf][nf][1] *= c0;
                O[mf][nf][2] *= c1; O[mf][nf][3] *= c1;
            }
        }

        // ---- O += P @ V (bf16x3; P in regs, V via trans-LDSM) ----
#pragma unroll 1
        for (int ks = 0; ks < 4; ks++) {
            unsigned aPH[2][4], aPL[2][4];
#pragma unroll
            for (int mf = 0; mf < 2; mf++) {
                splitp(sacc[mf][2 * ks][0],     sacc[mf][2 * ks][1],     aPH[mf][0], aPL[mf][0]);
                splitp(sacc[mf][2 * ks][2],     sacc[mf][2 * ks][3],     aPH[mf][1], aPL[mf][1]);
                splitp(sacc[mf][2 * ks + 1][0], sacc[mf][2 * ks + 1][1], aPH[mf][2], aPL[mf][2]);
                splitp(sacc[mf][2 * ks + 1][2], sacc[mf][2 * ks + 1][3], aPH[mf][3], aPL[mf][3]);
            }
            const unsigned kso = ks * (16 * FA_STR * 4);  // 16 key rows per ks
#pragma unroll
            for (int p = 0; p < 4; p++) {
                unsigned vh[4], vl[4];
                const unsigned po = p * 32;               // 8 u32 (16 hd) per p
                LDSM4T(vh[0], vh[1], vh[2], vh[3], vaH + kso + po);
                LDSM4T(vl[0], vl[1], vl[2], vl[3], vaL + kso + po);
#pragma unroll
                for (int mf = 0; mf < 2; mf++) {
                    mmabf(O[mf][2*p],   aPL[mf], vh[0], vh[1]);
                    mmabf(O[mf][2*p],   aPH[mf], vl[0], vl[1]);
                    mmabf(O[mf][2*p],   aPH[mf], vh[0], vh[1]);
                    mmabf(O[mf][2*p+1], aPL[mf], vh[2], vh[3]);
                    mmabf(O[mf][2*p+1], aPH[mf], vl[2], vl[3]);
                    mmabf(O[mf][2*p+1], aPH[mf], vh[2], vh[3]);
                }
            }
        }
    }

    // ---- epilogue -> g_attn[b,s,h*64+hd] ----
#pragma unroll
    for (int mf = 0; mf < 2; mf++) {
        const float inv0 = 1.f / la0[mf], inv1 = 1.f / la1[mf];
        const int s0r = q0 + qw + mf * 16 + g, s1r = s0r + 8;
        float* r0 = g_attn + ((size_t)b * Ssz + s0r) * Dsz + h * HDsz;
        float* r1 = g_attn + ((size_t)b * Ssz + s1r) * Dsz + h * HDsz;
#pragma unroll
        for (int nf = 0; nf < 8; nf++) {
            const int hd = nf * 8 + tig * 2;
            *(float2*)(r0 + hd) = make_float2(O[mf][nf][0] * inv0, O[mf][nf][1] * inv0);
            *(float2*)(r1 + hd) = make_float2(O[mf][nf][2] * inv1, O[mf][nf][3] * inv1);
        }
    }
}

// ---------------- LayerNorm over rows of 768 ----------------
__global__ void ln_v2(const float* __restrict__ gamma,
                      const float* __restrict__ beta,
                      float* __restrict__ out)
{
    __shared__ float red[256];
    const int row = blockIdx.x;
    const int t = threadIdx.x;
    const float* xr = g_x + (size_t)row * Dsz;

    float v[3];
    float s = 0.f;
#pragma unroll
    for (int i = 0; i < 3; i++) { v[i] = xr[t + i * 256]; s += v[i]; }
    red[t] = s; __syncthreads();
#pragma unroll
    for (int off = 128; off > 0; off >>= 1) {
        if (t < off) red[t] += red[t + off];
        __syncthreads();
    }
    float mean = red[0] * (1.f / 768.f);
    __syncthreads();

    float s2 = 0.f;
#pragma unroll
    for (int i = 0; i < 3; i++) { float d = v[i] - mean; s2 += d * d; }
    red[t] = s2; __syncthreads();
#pragma unroll
    for (int off = 128; off > 0; off >>= 1) {
        if (t < off) red[t] += red[t + off];
        __syncthreads();
    }
    float var = red[0] * (1.f / 768.f);
    float inv = rsqrtf(var + 1e-5f);

    float* orow = out + (size_t)row * Dsz;
#pragma unroll
    for (int i = 0; i < 3; i++) {
        int c = t + i * 256;
        orow[c] = (v[i] - mean) * inv * gamma[c] + beta[c];
    }
}

// ---------------- launch ----------------
extern "C" void kernel_launch(void* const* d_in, const int* in_sizes, int n_in,
                              void* d_out, int out_size)
{
    const float* context  = (const float*)d_in[0];
    const float* pad_mask = (const float*)d_in[1];
    const float* w_qkv    = (const float*)d_in[2];
    const float* w_proj   = (const float*)d_in[3];
    const float* b_proj   = (const float*)d_in[4];
    const float* gamma    = (const float*)d_in[5];
    const float* beta     = (const float*)d_in[6];
    float* out = (float*)d_out;

    cudaFuncSetAttribute(fa_tc4, cudaFuncAttributeMaxDynamicSharedMemorySize,
                         ATTN_SMEM_BYTES);

    qkv_b3<<<dim3(N_QKV / 64, MROWS / 128), 256>>>(context, w_qkv);
    fa_tc4<<<dim3(Ssz / 128, BH), 128, ATTN_SMEM_BYTES>>>(pad_mask);
    proj_b3<<<dim3(Dsz / 64, MROWS / 128), 256>>>(w_proj, b_proj, context);
    ln_v2<<<MROWS, 256>>>(gamma, beta, out);
}

// round 16
// speedup vs baseline: 1.4475x; 1.4475x over previous
#include <cuda_runtime.h>
#include <math.h>

#define Bsz 4
#define Ssz 2048
#define Dsz 768
#define Hsz 12
#define HDsz 64
#define BH (Bsz*Hsz)          // 48
#define MROWS (Bsz*Ssz)       // 8192
#define N_QKV (3*Dsz)         // 2304

// ---------------- scratch (no allocations allowed) ----------------
__device__ float g_Q[BH * Ssz * HDsz];   // [b,h,s,hd]
__device__ float g_K[BH * Ssz * HDsz];
__device__ float g_V[BH * Ssz * HDsz];
__device__ float g_attn[MROWS * Dsz];    // [b,s, h*64+hd]
__device__ float g_x[MROWS * Dsz];       // proj + bias + residual

// ---------------- bf16 split helpers ----------------
__device__ __forceinline__ float btrunc(float a) {
    return __uint_as_float(__float_as_uint(a) & 0xFFFF0000u);
}
__device__ __forceinline__ unsigned packbf(float ah, float bh) {
    return (__float_as_uint(ah) >> 16) | (__float_as_uint(bh) & 0xFFFF0000u);
}
__device__ __forceinline__ void splitp(float a, float b, unsigned& hp, unsigned& lp) {
    float ah = btrunc(a), bh = btrunc(b);
    hp = packbf(ah, bh);
    lp = packbf(btrunc(a - ah), btrunc(b - bh));
}
__device__ __forceinline__ void mmabf(float c[4], const unsigned a[4],
                                      unsigned b0, unsigned b1) {
    asm volatile(
        "mma.sync.aligned.m16n8k16.row.col.f32.bf16.bf16.f32 "
        "{%0,%1,%2,%3}, {%4,%5,%6,%7}, {%8,%9}, {%0,%1,%2,%3};\n"
        : "+f"(c[0]), "+f"(c[1]), "+f"(c[2]), "+f"(c[3])
        : "r"(a[0]), "r"(a[1]), "r"(a[2]), "r"(a[3]), "r"(b0), "r"(b1));
}

// ============================================================
// bf16x3 GEMM core: block 128x64, BK=32, 256 thr, warp tile 32x32.
// (R13 version: prefetch + B-fragment reuse — proven, unchanged)
// ============================================================
__device__ __forceinline__ void bf3_core(
    const float* __restrict__ A, const float* __restrict__ Bw,
    int NN, int m0, int n0, float acc[2][4][4],
    unsigned AH[128][17], unsigned AL[128][17],
    unsigned BHs[64][17], unsigned BLs[64][17])
{
    const int tid  = threadIdx.x;
    const int lane = tid & 31, wid = tid >> 5;
    const int g = lane >> 2, tig = lane & 3;
    const int wm = wid >> 1, wn = wid & 1;

    const int mA = tid >> 1, kqA = (tid & 1) * 16;
    const float* Ap = A + (size_t)(m0 + mA) * Dsz + kqA;
    const int kpB = tid >> 4, nqB = (tid & 15) * 4;
    const float* Bp = Bw + (size_t)(2 * kpB) * NN + n0 + nqB;

#pragma unroll
    for (int i = 0; i < 2; i++)
#pragma unroll
        for (int j = 0; j < 4; j++)
#pragma unroll
            for (int r = 0; r < 4; r++) acc[i][j][r] = 0.f;

    float4 a0 = *(const float4*)(Ap);
    float4 a1 = *(const float4*)(Ap + 4);
    float4 a2 = *(const float4*)(Ap + 8);
    float4 a3 = *(const float4*)(Ap + 12);
    float4 b0 = *(const float4*)(Bp);
    float4 b1 = *(const float4*)(Bp + NN);

#pragma unroll 1
    for (int it = 0; it < Dsz / 32; it++) {
        const int kp = kqA >> 1;
        splitp(a0.x, a0.y, AH[mA][kp+0], AL[mA][kp+0]);
        splitp(a0.z, a0.w, AH[mA][kp+1], AL[mA][kp+1]);
        splitp(a1.x, a1.y, AH[mA][kp+2], AL[mA][kp+2]);
        splitp(a1.z, a1.w, AH[mA][kp+3], AL[mA][kp+3]);
        splitp(a2.x, a2.y, AH[mA][kp+4], AL[mA][kp+4]);
        splitp(a2.z, a2.w, AH[mA][kp+5], AL[mA][kp+5]);
        splitp(a3.x, a3.y, AH[mA][kp+6], AL[mA][kp+6]);
        splitp(a3.z, a3.w, AH[mA][kp+7], AL[mA][kp+7]);
        splitp(b0.x, b1.x, BHs[nqB+0][kpB], BLs[nqB+0][kpB]);
        splitp(b0.y, b1.y, BHs[nqB+1][kpB], BLs[nqB+1][kpB]);
        splitp(b0.z, b1.z, BHs[nqB+2][kpB], BLs[nqB+2][kpB]);
        splitp(b0.w, b1.w, BHs[nqB+3][kpB], BLs[nqB+3][kpB]);
        __syncthreads();

        if (it + 1 < Dsz / 32) {
            const int k1 = (it + 1) * 32;
            a0 = *(const float4*)(Ap + k1);
            a1 = *(const float4*)(Ap + k1 + 4);
            a2 = *(const float4*)(Ap + k1 + 8);
            a3 = *(const float4*)(Ap + k1 + 12);
            b0 = *(const float4*)(Bp + (size_t)k1 * NN);
            b1 = *(const float4*)(Bp + (size_t)k1 * NN + NN);
        }

#pragma unroll
        for (int ks = 0; ks < 2; ks++) {
            const int kb = ks * 8;
            unsigned aH[2][4], aL[2][4];
#pragma unroll
            for (int mf = 0; mf < 2; mf++) {
                const int row = wm * 32 + mf * 16 + g;
                aH[mf][0] = AH[row][kb + tig];         aL[mf][0] = AL[row][kb + tig];
                aH[mf][1] = AH[row + 8][kb + tig];     aL[mf][1] = AL[row + 8][kb + tig];
                aH[mf][2] = AH[row][kb + 4 + tig];     aL[mf][2] = AL[row][kb + 4 + tig];
                aH[mf][3] = AH[row + 8][kb + 4 + tig]; aL[mf][3] = AL[row + 8][kb + 4 + tig];
            }
#pragma unroll
            for (int nf = 0; nf < 4; nf++) {
                const int n = wn * 32 + nf * 8 + g;
                unsigned bH0 = BHs[n][kb + tig], bH1 = BHs[n][kb + 4 + tig];
                unsigned bL0 = BLs[n][kb + tig], bL1 = BLs[n][kb + 4 + tig];
#pragma unroll
                for (int mf = 0; mf < 2; mf++) {
                    mmabf(acc[mf][nf], aL[mf], bH0, bH1);
                    mmabf(acc[mf][nf], aH[mf], bL0, bL1);
                    mmabf(acc[mf][nf], aH[mf], bH0, bH1);
                }
            }
        }
        __syncthreads();
    }
}

// ---------------- QKV GEMM -> scatter to g_Q/g_K/g_V ----------------
__global__ void __launch_bounds__(256)
qkv_b3(const float* __restrict__ A, const float* __restrict__ Bw)
{
    __shared__ unsigned AH[128][17], AL[128][17];
    __shared__ unsigned BHs[64][17], BLs[64][17];

    const int m0 = blockIdx.y * 128, n0 = blockIdx.x * 64;
    float acc[2][4][4];
    bf3_core(A, Bw, N_QKV, m0, n0, acc, AH, AL, BHs, BLs);

    const int tid = threadIdx.x;
    const int lane = tid & 31, wid = tid >> 5;
    const int g = lane >> 2, tig = lane & 3;
    const int wm = wid >> 1, wn = wid & 1;

    const int nbase = n0 + wn * 32;
    const int which = nbase / Dsz;
    const int h = (nbase % Dsz) >> 6;
    const int hd0 = (nbase % Dsz) & 63;
    float* dst = (which == 0) ? g_Q : (which == 1) ? g_K : g_V;
#pragma unroll
    for (int mf = 0; mf < 2; mf++) {
        const int m = m0 + wm * 32 + mf * 16 + g;
        const int b = m >> 11, s = m & 2047;
        float* r0 = dst + ((size_t)(b * Hsz + h) * Ssz + s) * HDsz + hd0;
        float* r1 = r0 + 8 * HDsz;
#pragma unroll
        for (int nf = 0; nf < 4; nf++) {
            const int hd = nf * 8 + tig * 2;
            *(float2*)(r0 + hd) = make_float2(acc[mf][nf][0], acc[mf][nf][1]);
            *(float2*)(r1 + hd) = make_float2(acc[mf][nf][2], acc[mf][nf][3]);
        }
    }
}

// ---------------- proj GEMM -> g_x = acc + bias + resid ----------------
__global__ void __launch_bounds__(256)
proj_b3(const float* __restrict__ Bw, const float* __restrict__ bias,
        const float* __restrict__ resid)
{
    __shared__ unsigned AH[128][17], AL[128][17];
    __shared__ unsigned BHs[64][17], BLs[64][17];

    const int m0 = blockIdx.y * 128, n0 = blockIdx.x * 64;
    float acc[2][4][4];
    bf3_core(g_attn, Bw, Dsz, m0, n0, acc, AH, AL, BHs, BLs);

    const int tid = threadIdx.x;
    const int lane = tid & 31, wid = tid >> 5;
    const int g = lane >> 2, tig = lane & 3;
    const int wm = wid >> 1, wn = wid & 1;

#pragma unroll
    for (int mf = 0; mf < 2; mf++) {
        const int m = m0 + wm * 32 + mf * 16 + g;
#pragma unroll
        for (int nf = 0; nf < 4; nf++) {
            const int n = n0 + wn * 32 + nf * 8 + tig * 2;
            float2 bv  = *(const float2*)(bias + n);
            float2 rv0 = *(const float2*)(resid + (size_t)m * Dsz + n);
            float2 rv1 = *(const float2*)(resid + (size_t)(m + 8) * Dsz + n);
            *(float2*)(g_x + (size_t)m * Dsz + n) =
                make_float2(acc[mf][nf][0] + bv.x + rv0.x, acc[mf][nf][1] + bv.y + rv0.y);
            *(float2*)(g_x + (size_t)(m + 8) * Dsz + n) =
                make_float2(acc[mf][nf][2] + bv.x + rv1.x, acc[mf][nf][3] + bv.y + rv1.y);
        }
    }
}

// ============================================================
// Flash attention, bf16x3 HMMA. 128 thr (4 warps), q-tile 128
// (warp 32 q-rows, mf=2), k-tile 64. CONFLICT-FREE strides:
// Q/K pair arrays stride 36 u32 (4g+tig banks), Vt stride 72 ushorts.
// ============================================================
#define QK_STR 36
#define VT_STR 72
#define ATTN_SMEM_BYTES ((2*128*QK_STR + 2*64*QK_STR + 64*VT_STR + 64) * 4)  // 73984 B

__global__ void __launch_bounds__(128)
fa_tc5(const float* __restrict__ pad_mask)
{
    extern __shared__ unsigned smu[];
    unsigned* QsH = smu;                        // [128][36]
    unsigned* QsL = QsH + 128 * QK_STR;
    unsigned* KsH = QsL + 128 * QK_STR;         // [64][36]
    unsigned* KsL = KsH + 64 * QK_STR;
    unsigned short* VtH = (unsigned short*)(KsL + 64 * QK_STR);  // bf16 [64][72]
    unsigned short* VtL = VtH + 64 * VT_STR;
    float* msk = (float*)(smu + 2 * 128 * QK_STR + 2 * 64 * QK_STR + 64 * VT_STR);

    const int tid  = threadIdx.x;
    const int lane = tid & 31, wid = tid >> 5;
    const int g = lane >> 2, tig = lane & 3;
    const int qw = wid * 32;
    const int q0 = blockIdx.x * 128;
    const int bh = blockIdx.y;
    const int b = bh / Hsz, h = bh % Hsz;

    const float* Qg = g_Q + ((size_t)bh * Ssz + q0) * HDsz;
    const float* Kg = g_K + (size_t)bh * Ssz * HDsz;
    const float* Vg = g_V + (size_t)bh * Ssz * HDsz;
    const float* mk = pad_mask + b * Ssz;

    // ---- load Q tile (scaled by 1/8), split into packed hi/lo k-pairs ----
#pragma unroll
    for (int i = 0; i < 16; i++) {
        int idx = tid + i * 128;
        int r = idx >> 4, c4 = (idx & 15) * 4;
        float4 v = *(const float4*)(Qg + r * HDsz + c4);
        v.x *= 0.125f; v.y *= 0.125f; v.z *= 0.125f; v.w *= 0.125f;
        int kp = r * QK_STR + (c4 >> 1);
        splitp(v.x, v.y, QsH[kp],     QsL[kp]);
        splitp(v.z, v.w, QsH[kp + 1], QsL[kp + 1]);
    }

    float O[2][8][4];
#pragma unroll
    for (int mf = 0; mf < 2; mf++)
#pragma unroll
        for (int i = 0; i < 8; i++)
#pragma unroll
            for (int j = 0; j < 4; j++) O[mf][i][j] = 0.f;
    float mr0[2], mr1[2], la0[2], la1[2];
#pragma unroll
    for (int mf = 0; mf < 2; mf++) { mr0[mf] = -1e30f; mr1[mf] = -1e30f; la0[mf] = 0.f; la1[mf] = 0.f; }

#pragma unroll 1
    for (int kt = 0; kt < Ssz / 64; kt++) {
        const int key0 = kt * 64;
        __syncthreads();
#pragma unroll
        for (int i = 0; i < 8; i++) {
            int idx = tid + i * 128;
            int r = idx >> 4, c4 = (idx & 15) * 4;
            float4 kv = *(const float4*)(Kg + (size_t)(key0 + r) * HDsz + c4);
            int kp = r * QK_STR + (c4 >> 1);
            splitp(kv.x, kv.y, KsH[kp],     KsL[kp]);
            splitp(kv.z, kv.w, KsH[kp + 1], KsL[kp + 1]);
            float4 vv = *(const float4*)(Vg + (size_t)(key0 + r) * HDsz + c4);
#pragma unroll
            for (int q = 0; q < 4; q++) {
                float x = (&vv.x)[q];
                float hh = btrunc(x);
                VtH[(c4 + q) * VT_STR + r] = (unsigned short)(__float_as_uint(hh) >> 16);
                VtL[(c4 + q) * VT_STR + r] = (unsigned short)(__float_as_uint(btrunc(x - hh)) >> 16);
            }
        }
        if (tid < 64) msk[tid] = mk[key0 + tid];
        __syncthreads();

        // ---- S = Q @ K^T (bf16x3), 2 mf sub-tiles share K fragments ----
        float sacc[2][8][4];
#pragma unroll
        for (int mf = 0; mf < 2; mf++)
#pragma unroll
            for (int i = 0; i < 8; i++)
#pragma unroll
                for (int j = 0; j < 4; j++) sacc[mf][i][j] = 0.f;
#pragma unroll 1
        for (int ks = 0; ks < 4; ks++) {
            const int kb = ks * 8;
            unsigned aH[2][4], aL[2][4];
#pragma unroll
            for (int mf = 0; mf < 2; mf++) {
                const int row = qw + mf * 16 + g;
                aH[mf][0] = QsH[row * QK_STR + kb + tig];
                aH[mf][1] = QsH[(row + 8) * QK_STR + kb + tig];
                aH[mf][2] = QsH[row * QK_STR + kb + 4 + tig];
                aH[mf][3] = QsH[(row + 8) * QK_STR + kb + 4 + tig];
                aL[mf][0] = QsL[row * QK_STR + kb + tig];
                aL[mf][1] = QsL[(row + 8) * QK_STR + kb + tig];
                aL[mf][2] = QsL[row * QK_STR + kb + 4 + tig];
                aL[mf][3] = QsL[(row + 8) * QK_STR + kb + 4 + tig];
            }
#pragma unroll
            for (int nf = 0; nf < 8; nf++) {
                const int n = nf * 8 + g;
                unsigned bH0 = KsH[n * QK_STR + kb + tig];
                unsigned bH1 = KsH[n * QK_STR + kb + 4 + tig];
                unsigned bL0 = KsL[n * QK_STR + kb + tig];
                unsigned bL1 = KsL[n * QK_STR + kb + 4 + tig];
#pragma unroll
                for (int mf = 0; mf < 2; mf++) {
                    mmabf(sacc[mf][nf], aL[mf], bH0, bH1);
                    mmabf(sacc[mf][nf], aH[mf], bL0, bL1);
                    mmabf(sacc[mf][nf], aH[mf], bH0, bH1);
                }
            }
        }

        // ---- mask (scale already folded into Q) ----
#pragma unroll
        for (int nf = 0; nf < 8; nf++) {
            float mv0 = msk[nf * 8 + tig * 2];
            float mv1 = msk[nf * 8 + tig * 2 + 1];
#pragma unroll
            for (int mf = 0; mf < 2; mf++) {
                sacc[mf][nf][0] = sacc[mf][nf][0] * mv0 - (1.f - mv0) * 1e10f;
                sacc[mf][nf][1] = sacc[mf][nf][1] * mv1 - (1.f - mv1) * 1e10f;
                sacc[mf][nf][2] = sacc[mf][nf][2] * mv0 - (1.f - mv0) * 1e10f;
                sacc[mf][nf][3] = sacc[mf][nf][3] * mv1 - (1.f - mv1) * 1e10f;
            }
        }

        // ---- online softmax per mf ----
#pragma unroll
        for (int mf = 0; mf < 2; mf++) {
            float tm0 = -1e30f, tm1 = -1e30f;
#pragma unroll
            for (int nf = 0; nf < 8; nf++) {
                tm0 = fmaxf(tm0, fmaxf(sacc[mf][nf][0], sacc[mf][nf][1]));
                tm1 = fmaxf(tm1, fmaxf(sacc[mf][nf][2], sacc[mf][nf][3]));
            }
            tm0 = fmaxf(tm0, __shfl_xor_sync(0xffffffffu, tm0, 1));
            tm0 = fmaxf(tm0, __shfl_xor_sync(0xffffffffu, tm0, 2));
            tm1 = fmaxf(tm1, __shfl_xor_sync(0xffffffffu, tm1, 1));
            tm1 = fmaxf(tm1, __shfl_xor_sync(0xffffffffu, tm1, 2));
            float mn0 = fmaxf(mr0[mf], tm0), mn1 = fmaxf(mr1[mf], tm1);
            float c0 = __expf(mr0[mf] - mn0), c1 = __expf(mr1[mf] - mn1);
            float s0 = 0.f, s1 = 0.f;
#pragma unroll
            for (int nf = 0; nf < 8; nf++) {
                sacc[mf][nf][0] = __expf(sacc[mf][nf][0] - mn0);
                sacc[mf][nf][1] = __expf(sacc[mf][nf][1] - mn0);
                sacc[mf][nf][2] = __expf(sacc[mf][nf][2] - mn1);
                sacc[mf][nf][3] = __expf(sacc[mf][nf][3] - mn1);
                s0 += sacc[mf][nf][0] + sacc[mf][nf][1];
                s1 += sacc[mf][nf][2] + sacc[mf][nf][3];
            }
            s0 += __shfl_xor_sync(0xffffffffu, s0, 1);
            s0 += __shfl_xor_sync(0xffffffffu, s0, 2);
            s1 += __shfl_xor_sync(0xffffffffu, s1, 1);
            s1 += __shfl_xor_sync(0xffffffffu, s1, 2);
            la0[mf] = la0[mf] * c0 + s0;
            la1[mf] = la1[mf] * c1 + s1;
            mr0[mf] = mn0; mr1[mf] = mn1;
#pragma unroll
            for (int nf = 0; nf < 8; nf++) {
                O[mf][nf][0] *= c0; O[mf][nf][1] *= c0;
                O[mf][nf][2] *= c1; O[mf][nf][3] *= c1;
            }
        }

        // ---- O += P @ V (bf16x3, P in registers, V frags shared across mf) ----
#pragma unroll 1
        for (int ks = 0; ks < 4; ks++) {
            unsigned aPH[2][4], aPL[2][4];
#pragma unroll
            for (int mf = 0; mf < 2; mf++) {
                splitp(sacc[mf][2 * ks][0],     sacc[mf][2 * ks][1],     aPH[mf][0], aPL[mf][0]);
                splitp(sacc[mf][2 * ks][2],     sacc[mf][2 * ks][3],     aPH[mf][1], aPL[mf][1]);
                splitp(sacc[mf][2 * ks + 1][0], sacc[mf][2 * ks + 1][1], aPH[mf][2], aPL[mf][2]);
                splitp(sacc[mf][2 * ks + 1][2], sacc[mf][2 * ks + 1][3], aPH[mf][3], aPL[mf][3]);
            }
            const int kb = ks * 16 + 2 * tig;
#pragma unroll
            for (int nf = 0; nf < 8; nf++) {
                const int n = nf * 8 + g;
                unsigned bH0 = *(const unsigned*)(VtH + n * VT_STR + kb);
                unsigned bH1 = *(const unsigned*)(VtH + n * VT_STR + kb + 8);
                unsigned bL0 = *(const unsigned*)(VtL + n * VT_STR + kb);
                unsigned bL1 = *(const unsigned*)(VtL + n * VT_STR + kb + 8);
#pragma unroll
                for (int mf = 0; mf < 2; mf++) {
                    mmabf(O[mf][nf], aPL[mf], bH0, bH1);
                    mmabf(O[mf][nf], aPH[mf], bL0, bL1);
                    mmabf(O[mf][nf], aPH[mf], bH0, bH1);
                }
            }
        }
    }

    // ---- epilogue -> g_attn[b,s,h*64+hd] ----
#pragma unroll
    for (int mf = 0; mf < 2; mf++) {
        const float inv0 = 1.f / la0[mf], inv1 = 1.f / la1[mf];
        const int s0r = q0 + qw + mf * 16 + g, s1r = s0r + 8;
        float* r0 = g_attn + ((size_t)b * Ssz + s0r) * Dsz + h * HDsz;
        float* r1 = g_attn + ((size_t)b * Ssz + s1r) * Dsz + h * HDsz;
#pragma unroll
        for (int nf = 0; nf < 8; nf++) {
            const int hd = nf * 8 + tig * 2;
            *(float2*)(r0 + hd) = make_float2(O[mf][nf][0] * inv0, O[mf][nf][1] * inv0);
            *(float2*)(r1 + hd) = make_float2(O[mf][nf][2] * inv1, O[mf][nf][3] * inv1);
        }
    }
}

// ---------------- LayerNorm over rows of 768 ----------------
__global__ void ln_v2(const float* __restrict__ gamma,
                      const float* __restrict__ beta,
                      float* __restrict__ out)
{
    __shared__ float red[256];
    const int row = blockIdx.x;
    const int t = threadIdx.x;
    const float* xr = g_x + (size_t)row * Dsz;

    float v[3];
    float s = 0.f;
#pragma unroll
    for (int i = 0; i < 3; i++) { v[i] = xr[t + i * 256]; s += v[i]; }
    red[t] = s; __syncthreads();
#pragma unroll
    for (int off = 128; off > 0; off >>= 1) {
        if (t < off) red[t] += red[t + off];
        __syncthreads();
    }
    float mean = red[0] * (1.f / 768.f);
    __syncthreads();

    float s2 = 0.f;
#pragma unroll
    for (int i = 0; i < 3; i++) { float d = v[i] - mean; s2 += d * d; }
    red[t] = s2; __syncthreads();
#pragma unroll
    for (int off = 128; off > 0; off >>= 1) {
        if (t < off) red[t] += red[t + off];
        __syncthreads();
    }
    float var = red[0] * (1.f / 768.f);
    float inv = rsqrtf(var + 1e-5f);

    float* orow = out + (size_t)row * Dsz;
#pragma unroll
    for (int i = 0; i < 3; i++) {
        int c = t + i * 256;
        orow[c] = (v[i] - mean) * inv * gamma[c] + beta[c];
    }
}

// ---------------- launch ----------------
extern "C" void kernel_launch(void* const* d_in, const int* in_sizes, int n_in,
                              void* d_out, int out_size)
{
    const float* context  = (const float*)d_in[0];
    const float* pad_mask = (const float*)d_in[1];
    const float* w_qkv    = (const float*)d_in[2];
    const float* w_proj   = (const float*)d_in[3];
    const float* b_proj   = (const float*)d_in[4];
    const float* gamma    = (const float*)d_in[5];
    const float* beta     = (const float*)d_in[6];
    float* out = (float*)d_out;

    cudaFuncSetAttribute(fa_tc5, cudaFuncAttributeMaxDynamicSharedMemorySize,
                         ATTN_SMEM_BYTES);

    qkv_b3<<<dim3(N_QKV / 64, MROWS / 128), 256>>>(context, w_qkv);
    fa_tc5<<<dim3(Ssz / 128, BH), 128, ATTN_SMEM_BYTES>>>(pad_mask);
    proj_b3<<<dim3(Dsz / 64, MROWS / 128), 256>>>(w_proj, b_proj, context);
    ln_v2<<<MROWS, 256>>>(gamma, beta, out);
}